// round 1
// baseline (speedup 1.0000x reference)
#include <cuda_runtime.h>
#include <cstdint>

#define BATCH 512
#define IN0   784
#define HID   1024
#define NOUT  10
#define NT    32

// Scratch (no cudaMalloc allowed): device globals.
__device__ float g_cur0[BATCH * HID];   // layer-0 currents (time-invariant)
__device__ float g_w1t[HID * HID];      // W1 transposed: row i = column i of W1
__device__ float g_w2t[HID * 16];       // W2 transposed, padded stride 16

// ---------------------------------------------------------------------------
// Transpose W1 [1024,1024] -> g_w1t (coalesced via smem tile)
// ---------------------------------------------------------------------------
__global__ void transpose_w1_kernel(const float* __restrict__ W1) {
    __shared__ float tile[32][33];
    const int bx = blockIdx.x * 32, by = blockIdx.y * 32;
    const int tx = threadIdx.x, ty = threadIdx.y;
#pragma unroll
    for (int i = 0; i < 32; i += 8)
        tile[ty + i][tx] = W1[(by + ty + i) * HID + bx + tx];
    __syncthreads();
#pragma unroll
    for (int i = 0; i < 32; i += 8)
        g_w1t[(bx + ty + i) * HID + by + tx] = tile[tx][ty + i];
}

// Transpose W2 [10,1024] -> g_w2t [1024,16-padded]
__global__ void transpose_w2_kernel(const float* __restrict__ W2) {
    const int i = blockIdx.x * blockDim.x + threadIdx.x;  // 0..1023
#pragma unroll
    for (int j = 0; j < NOUT; j++)
        g_w2t[i * 16 + j] = W2[j * HID + i];
}

// ---------------------------------------------------------------------------
// GEMM0: g_cur0[b,o] = dot(x[b,:], W0[o,:]) + b0[o]
// Both operands K-major (NT gemm). 64x64 tile, BK=16, 256 threads, 4x4/thread.
// ---------------------------------------------------------------------------
__global__ void __launch_bounds__(256) gemm0_kernel(
    const float* __restrict__ X,     // [512,784]
    const float* __restrict__ W,     // [1024,784]
    const float* __restrict__ bias)  // [1024]
{
    __shared__ float As[16][68];  // [k][m], padded
    __shared__ float Bs[16][68];  // [k][n], padded
    const int bm = blockIdx.y * 64, bn = blockIdx.x * 64;
    const int tid = threadIdx.x;
    const int tx = tid & 15, ty = tid >> 4;
    const int lrow = tid >> 2, lc = (tid & 3) * 4;

    float acc[4][4];
#pragma unroll
    for (int r = 0; r < 4; r++)
#pragma unroll
        for (int c = 0; c < 4; c++) acc[r][c] = 0.f;

    for (int k0 = 0; k0 < IN0; k0 += 16) {
        float4 a = *(const float4*)(X + (bm + lrow) * IN0 + k0 + lc);
        float4 w = *(const float4*)(W + (bn + lrow) * IN0 + k0 + lc);
        As[lc + 0][lrow] = a.x; As[lc + 1][lrow] = a.y;
        As[lc + 2][lrow] = a.z; As[lc + 3][lrow] = a.w;
        Bs[lc + 0][lrow] = w.x; Bs[lc + 1][lrow] = w.y;
        Bs[lc + 2][lrow] = w.z; Bs[lc + 3][lrow] = w.w;
        __syncthreads();
#pragma unroll
        for (int kk = 0; kk < 16; kk++) {
            float4 av = *(const float4*)&As[kk][ty * 4];
            float4 bv = *(const float4*)&Bs[kk][tx * 4];
            float am[4] = {av.x, av.y, av.z, av.w};
            float bb[4] = {bv.x, bv.y, bv.z, bv.w};
#pragma unroll
            for (int r = 0; r < 4; r++)
#pragma unroll
                for (int c = 0; c < 4; c++) acc[r][c] += am[r] * bb[c];
        }
        __syncthreads();
    }
#pragma unroll
    for (int r = 0; r < 4; r++)
#pragma unroll
        for (int c = 0; c < 4; c++)
            g_cur0[(bm + ty * 4 + r) * HID + bn + tx * 4 + c] =
                acc[r][c] + bias[bn + tx * 4 + c];
}

// ---------------------------------------------------------------------------
// Fused temporal SNN: one block per batch element b.
// 256 threads, each owns 4 neurons (o = tid + j*256) of layers 0 and 1.
// Spike exchange via 1024-bit shared bitmasks (ballot -> deterministic,
// ascending-index fp32 accumulation order).
// Layer-1 current = sum over set bits i of g_w1t row i (coalesced 4KB rows,
// L2-resident). Layer-2 (10 outputs) handled by threads 0..9.
// ---------------------------------------------------------------------------
__global__ void __launch_bounds__(256) snn_kernel(
    const float* __restrict__ b1,
    const float* __restrict__ b2,
    float* __restrict__ out)  // [512,10]
{
    const int b = blockIdx.x;
    const int tid = threadIdx.x;
    const int lane = tid & 31, warp = tid >> 5;

    __shared__ unsigned mask0[32];
    __shared__ unsigned mask1[32];

    float v0[4], v1[4], c0[4], b1r[4];
#pragma unroll
    for (int j = 0; j < 4; j++) {
        v0[j] = 0.f;
        v1[j] = 0.f;
        c0[j] = g_cur0[b * HID + tid + j * 256];
        b1r[j] = b1[tid + j * 256];
    }
    float v2 = 0.f, cnt = 0.f, b2r = 0.f;
    if (tid < NOUT) b2r = b2[tid];

    for (int t = 0; t < NT; t++) {
        // ---- layer 0 LIF (constant input c0) ----
#pragma unroll
        for (int j = 0; j < 4; j++) {
            v0[j] += (c0[j] - v0[j]) * 0.5f;       // == v + (x-v)/2 exactly
            bool s = v0[j] >= 1.0f;
            unsigned bal = __ballot_sync(0xffffffffu, s);
            if (s) v0[j] = 0.f;                     // hard reset
            if (lane == 0) mask0[warp + j * 8] = bal;  // word (o>>5), bit (o&31)
        }
        __syncthreads();

        // ---- layer 1 current: gather active W1^T rows ----
        float c1[4] = {b1r[0], b1r[1], b1r[2], b1r[3]};
#pragma unroll 1
        for (int w = 0; w < 32; w++) {
            unsigned mm = mask0[w];
            while (mm) {
                int bit = __ffs(mm) - 1;
                mm &= mm - 1;
                const float* row = g_w1t + (unsigned)(w * 32 + bit) * HID + tid;
#pragma unroll
                for (int j = 0; j < 4; j++) c1[j] += __ldg(row + j * 256);
            }
        }

        // ---- layer 1 LIF ----
#pragma unroll
        for (int j = 0; j < 4; j++) {
            v1[j] += (c1[j] - v1[j]) * 0.5f;
            bool s = v1[j] >= 1.0f;
            unsigned bal = __ballot_sync(0xffffffffu, s);
            if (s) v1[j] = 0.f;
            if (lane == 0) mask1[warp + j * 8] = bal;
        }
        __syncthreads();

        // ---- layer 2 current + LIF + spike count (threads 0..9) ----
        if (tid < NOUT) {
            float c2 = b2r;
#pragma unroll 1
            for (int w = 0; w < 32; w++) {
                unsigned mm = mask1[w];
                while (mm) {
                    int bit = __ffs(mm) - 1;
                    mm &= mm - 1;
                    c2 += g_w2t[(unsigned)(w * 32 + bit) * 16 + tid];
                }
            }
            v2 += (c2 - v2) * 0.5f;
            if (v2 >= 1.0f) { cnt += 1.0f; v2 = 0.f; }
        }
        __syncthreads();  // protects mask0/mask1 reuse next iteration
    }

    if (tid < NOUT) out[b * NOUT + tid] = cnt;
}

// ---------------------------------------------------------------------------
extern "C" void kernel_launch(void* const* d_in, const int* in_sizes, int n_in,
                              void* d_out, int out_size) {
    const float* x  = (const float*)d_in[0];  // [512,784]
    const float* W0 = (const float*)d_in[1];  // [1024,784]
    const float* b0 = (const float*)d_in[2];  // [1024]
    const float* W1 = (const float*)d_in[3];  // [1024,1024]
    const float* b1 = (const float*)d_in[4];  // [1024]
    const float* W2 = (const float*)d_in[5];  // [10,1024]
    const float* b2 = (const float*)d_in[6];  // [10]
    float* out = (float*)d_out;               // [512,10] float32

    transpose_w1_kernel<<<dim3(32, 32), dim3(32, 8)>>>(W1);
    transpose_w2_kernel<<<1, HID>>>(W2);
    gemm0_kernel<<<dim3(HID / 64, BATCH / 64), 256>>>(x, W0, b0);
    snn_kernel<<<BATCH, 256>>>(b1, b2, out);
}

// round 2
// speedup vs baseline: 2.0862x; 2.0862x over previous
#include <cuda_runtime.h>
#include <cstdint>

#define BATCH 512
#define IN0   784
#define HID   1024
#define NOUT  10
#define NT    32

// Scratch (no cudaMalloc allowed): device globals.
__device__ float g_cur0[BATCH * HID];   // layer-0 currents (time-invariant)
__device__ float g_w1t[HID * HID];      // W1 transposed: row i = column i of W1
__device__ float g_w2t[HID * 16];       // W2 transposed, padded stride 16

// ---------------------------------------------------------------------------
// Transpose W1 [1024,1024] -> g_w1t; block (0,0) also transposes W2.
// ---------------------------------------------------------------------------
__global__ void transpose_kernel(const float* __restrict__ W1,
                                 const float* __restrict__ W2) {
    __shared__ float tile[32][33];
    const int bx = blockIdx.x * 32, by = blockIdx.y * 32;
    const int tx = threadIdx.x, ty = threadIdx.y;
#pragma unroll
    for (int i = 0; i < 32; i += 8)
        tile[ty + i][tx] = W1[(by + ty + i) * HID + bx + tx];
    __syncthreads();
#pragma unroll
    for (int i = 0; i < 32; i += 8)
        g_w1t[(bx + ty + i) * HID + by + tx] = tile[tx][ty + i];

    if (blockIdx.x == 0 && blockIdx.y == 0) {
        const int t = ty * 32 + tx;  // 0..255
#pragma unroll
        for (int r = 0; r < 4; r++) {
            const int i = t + r * 256;
#pragma unroll
            for (int j = 0; j < NOUT; j++)
                g_w2t[i * 16 + j] = W2[j * HID + i];
        }
    }
}

// ---------------------------------------------------------------------------
// GEMM0: g_cur0[b,o] = dot(x[b,:], W0[o,:]) + b0[o]   (near fp32 FMA floor)
// ---------------------------------------------------------------------------
__global__ void __launch_bounds__(256) gemm0_kernel(
    const float* __restrict__ X,     // [512,784]
    const float* __restrict__ W,     // [1024,784]
    const float* __restrict__ bias)  // [1024]
{
    __shared__ float As[16][68];  // [k][m], padded
    __shared__ float Bs[16][68];  // [k][n], padded
    const int bm = blockIdx.y * 64, bn = blockIdx.x * 64;
    const int tid = threadIdx.x;
    const int tx = tid & 15, ty = tid >> 4;
    const int lrow = tid >> 2, lc = (tid & 3) * 4;

    float acc[4][4];
#pragma unroll
    for (int r = 0; r < 4; r++)
#pragma unroll
        for (int c = 0; c < 4; c++) acc[r][c] = 0.f;

    for (int k0 = 0; k0 < IN0; k0 += 16) {
        float4 a = *(const float4*)(X + (bm + lrow) * IN0 + k0 + lc);
        float4 w = *(const float4*)(W + (bn + lrow) * IN0 + k0 + lc);
        As[lc + 0][lrow] = a.x; As[lc + 1][lrow] = a.y;
        As[lc + 2][lrow] = a.z; As[lc + 3][lrow] = a.w;
        Bs[lc + 0][lrow] = w.x; Bs[lc + 1][lrow] = w.y;
        Bs[lc + 2][lrow] = w.z; Bs[lc + 3][lrow] = w.w;
        __syncthreads();
#pragma unroll
        for (int kk = 0; kk < 16; kk++) {
            float4 av = *(const float4*)&As[kk][ty * 4];
            float4 bv = *(const float4*)&Bs[kk][tx * 4];
            float am[4] = {av.x, av.y, av.z, av.w};
            float bb[4] = {bv.x, bv.y, bv.z, bv.w};
#pragma unroll
            for (int r = 0; r < 4; r++)
#pragma unroll
                for (int c = 0; c < 4; c++) acc[r][c] += am[r] * bb[c];
        }
        __syncthreads();
    }
#pragma unroll
    for (int r = 0; r < 4; r++)
#pragma unroll
        for (int c = 0; c < 4; c++)
            g_cur0[(bm + ty * 4 + r) * HID + bn + tx * 4 + c] =
                acc[r][c] + bias[bn + tx * 4 + c];
}

// ---------------------------------------------------------------------------
// Fused temporal SNN, v2: one block (512 threads) per batch element.
// Each thread owns 2 neurons (tid, tid+512) of layers 0 and 1.
// - Layer-0 spike masks for ALL 32 timesteps precomputed up front (input is
//   time-constant), stored as bitmasks in smem.
// - Per timestep, warp 0 compacts the mask into an ascending spike-index
//   list (deterministic order); all threads then gather only active W1^T
//   rows (L2-resident, coalesced).
// - Layer 2 (10 outputs) handled by warp 0 lanes 0..9 from a second list.
// Only 2 __syncthreads per timestep (ordering proof: every smem buffer's
// writer at t+1 is separated from its readers at t by one of the barriers).
// ---------------------------------------------------------------------------
__global__ void __launch_bounds__(512, 4) snn_kernel(
    const float* __restrict__ b1,
    const float* __restrict__ b2,
    float* __restrict__ out)  // [512,10]
{
    const int b = blockIdx.x;
    const int tid = threadIdx.x;
    const int lane = tid & 31, warp = tid >> 5;

    __shared__ unsigned maskAll[NT][32];        // layer-0 spikes, all timesteps
    __shared__ unsigned mask1[32];              // layer-1 spikes, current t
    __shared__ unsigned short list0[HID];
    __shared__ unsigned short list1[HID];
    __shared__ int sh_n0;

    float v0[2] = {0.f, 0.f}, v1[2] = {0.f, 0.f}, c0[2], b1r[2];
#pragma unroll
    for (int j = 0; j < 2; j++) {
        c0[j]  = g_cur0[b * HID + tid + j * 512];
        b1r[j] = b1[tid + j * 512];
    }
    float v2 = 0.f, cnt = 0.f, b2r = 0.f;
    if (tid < NOUT) b2r = b2[tid];

    // ---- precompute ALL layer-0 spike masks (input is constant in t) ----
    for (int t = 0; t < NT; t++) {
#pragma unroll
        for (int j = 0; j < 2; j++) {
            v0[j] += (c0[j] - v0[j]) * 0.5f;        // == v + (x - v)/2 exactly
            bool s = v0[j] >= 1.0f;
            unsigned bal = __ballot_sync(0xffffffffu, s);
            if (s) v0[j] = 0.f;
            if (lane == 0) maskAll[t][warp + j * 16] = bal;
        }
    }
    __syncthreads();

    for (int t = 0; t < NT; t++) {
        // ---- warp 0: compact layer-0 mask into ascending index list ----
        if (warp == 0) {
            unsigned m = maskAll[t][lane];
            int c = __popc(m);
            int inc = c;
#pragma unroll
            for (int d = 1; d < 32; d <<= 1) {
                int y = __shfl_up_sync(0xffffffffu, inc, d);
                if (lane >= d) inc += y;
            }
            int total = __shfl_sync(0xffffffffu, inc, 31);
            int base = inc - c;
            const int nb = lane * 32;
            while (m) {
                int bb = __ffs(m) - 1;
                m &= m - 1;
                list0[base++] = (unsigned short)(nb + bb);
            }
            if (lane == 31) sh_n0 = total;
        }
        __syncthreads();  // B1: list0 / sh_n0 ready

        // ---- layer-1 current: gather active W1^T rows ----
        const int n0 = sh_n0;
        float c1a = b1r[0], c1b = b1r[1];
        for (int k = 0; k < n0; k++) {
            const int idx = list0[k];                        // smem broadcast
            const float* row = g_w1t + (unsigned)idx * HID;
            c1a += __ldg(row + tid);
            c1b += __ldg(row + tid + 512);
        }

        // ---- layer-1 LIF ----
        {
            v1[0] += (c1a - v1[0]) * 0.5f;
            bool s = v1[0] >= 1.0f;
            unsigned bal = __ballot_sync(0xffffffffu, s);
            if (s) v1[0] = 0.f;
            if (lane == 0) mask1[warp] = bal;

            v1[1] += (c1b - v1[1]) * 0.5f;
            s = v1[1] >= 1.0f;
            bal = __ballot_sync(0xffffffffu, s);
            if (s) v1[1] = 0.f;
            if (lane == 0) mask1[warp + 16] = bal;
        }
        __syncthreads();  // B2: mask1 ready

        // ---- warp 0: layer-2 (list build + gather + LIF + count) ----
        if (warp == 0) {
            unsigned m = mask1[lane];
            int c = __popc(m);
            int inc = c;
#pragma unroll
            for (int d = 1; d < 32; d <<= 1) {
                int y = __shfl_up_sync(0xffffffffu, inc, d);
                if (lane >= d) inc += y;
            }
            int total = __shfl_sync(0xffffffffu, inc, 31);
            int base = inc - c;
            const int nb = lane * 32;
            while (m) {
                int bb = __ffs(m) - 1;
                m &= m - 1;
                list1[base++] = (unsigned short)(nb + bb);
            }
            __syncwarp();
            if (lane < NOUT) {
                float c2 = b2r;
                for (int k = 0; k < total; k++)
                    c2 += g_w2t[(unsigned)list1[k] * 16 + lane];
                v2 += (c2 - v2) * 0.5f;
                if (v2 >= 1.0f) { cnt += 1.0f; v2 = 0.f; }
            }
        }
        // no third barrier needed: warp 0 finishes reading mask1/list1 before
        // it reaches B1 of t+1, and other warps only rewrite mask1 after B1.
    }

    if (tid < NOUT) out[b * NOUT + tid] = cnt;
}

// ---------------------------------------------------------------------------
extern "C" void kernel_launch(void* const* d_in, const int* in_sizes, int n_in,
                              void* d_out, int out_size) {
    const float* x  = (const float*)d_in[0];  // [512,784]
    const float* W0 = (const float*)d_in[1];  // [1024,784]
    const float* b0 = (const float*)d_in[2];  // [1024]
    const float* W1 = (const float*)d_in[3];  // [1024,1024]
    const float* b1 = (const float*)d_in[4];  // [1024]
    const float* W2 = (const float*)d_in[5];  // [10,1024]
    const float* b2 = (const float*)d_in[6];  // [10]
    float* out = (float*)d_out;               // [512,10] float32

    transpose_kernel<<<dim3(32, 32), dim3(32, 8)>>>(W1, W2);
    gemm0_kernel<<<dim3(HID / 64, BATCH / 64), 256>>>(x, W0, b0);
    snn_kernel<<<BATCH, 512>>>(b1, b2, out);
}